// round 14
// baseline (speedup 1.0000x reference)
#include <cuda_runtime.h>
#include <cuda_fp16.h>
#include <math.h>
#include <stdint.h>

// ---------------------------------------------------------------------------
// Problem constants
// ---------------------------------------------------------------------------
#define NN        87381     // total nodes = (4^9-1)/3
#define NI        21845     // internal nodes
#define LEAF_N    65536
#define LEAF_S    21845

// ---------------------------------------------------------------------------
// Device scratch (static — no allocation allowed)
// ---------------------------------------------------------------------------
__device__ __half g_xiou[NN * 768];          // iou preactivations (fp16)
__device__ __half g_xfq[NI * 512];           // cols 0-255: x_f, 256-511: q
__device__ __half g_hu[16384 * 1024];        // cols 0-767: h_iou, 768-1023: h_f
__device__ __half g_kkvv[65536 * 512];       // cols 0-255: k, 256-511: v
__device__ __half g_att[16384 * 256];
__device__ __half g_xh[NN * 256];            // x as fp16
__device__ __half g_hh[NN * 256];            // h as fp16

// weight rows (transposed fp16). row index == bias index.
#define WT_IOU  0       // 768 rows
#define WT_FQ   768     // 512 rows (f, q)
#define WT_KV   1280    // 512 rows (k, v)
#define WT_L    1792    // 256 rows (unused by HMMA path after folding; kept)
#define WT_U    2048    // 1024 rows (uiou, uf) — used to BUILD wcomb
__device__ __half g_wthi[3072 * 256];
__device__ float  g_bias[3072];

// folded Wl*U weights: 1024 rows x 256 k (fp16), fused bias, plain-Wl fp16
__device__ __half g_wcombt[1024 * 256];
__device__ float  g_bcomb[1024];
__device__ __half g_wlplain[256 * 256];
__device__ float  g_zbias[256];              // zero-initialized by CUDA

// ---------------------------------------------------------------------------
// PTX helpers (sm_80+ — safe for plain sm_103 ptxas target)
// ---------------------------------------------------------------------------
__device__ __forceinline__ uint32_t s2u(const void* p) {
    uint32_t a;
    asm("{ .reg .u64 t; cvta.to.shared.u64 t, %1; cvt.u32.u64 %0, t; }"
        : "=r"(a) : "l"(p));
    return a;
}
__device__ __forceinline__ void cpa16(uint32_t dst, const void* src, int nbytes) {
    asm volatile("cp.async.cg.shared.global [%0], [%1], 16, %2;"
                 :: "r"(dst), "l"(src), "r"(nbytes) : "memory");
}
__device__ __forceinline__ void cpa_commit() {
    asm volatile("cp.async.commit_group;" ::: "memory");
}
__device__ __forceinline__ void ldm4(uint32_t* r, uint32_t addr) {
    asm volatile("ldmatrix.sync.aligned.m8n8.x4.shared.b16 {%0,%1,%2,%3}, [%4];"
                 : "=r"(r[0]), "=r"(r[1]), "=r"(r[2]), "=r"(r[3]) : "r"(addr));
}
__device__ __forceinline__ void mma16816(float* c, const uint32_t* a, const uint32_t* b) {
    asm volatile(
        "mma.sync.aligned.m16n8k16.row.col.f32.f16.f16.f32 "
        "{%0,%1,%2,%3}, {%4,%5,%6,%7}, {%8,%9}, {%0,%1,%2,%3};"
        : "+f"(c[0]), "+f"(c[1]), "+f"(c[2]), "+f"(c[3])
        : "r"(a[0]), "r"(a[1]), "r"(a[2]), "r"(a[3]), "r"(b[0]), "r"(b[1]));
}
__device__ __forceinline__ uint32_t swadr(uint32_t base, int row, int gran) {
    return base + row * 128 + ((gran ^ (row & 7)) << 4);
}
__device__ __forceinline__ uint32_t packh(__half a, __half b) {
    return ((uint32_t)__half_as_ushort(b) << 16) | __half_as_ushort(a);
}
__device__ __forceinline__ float sigm(float x) { return 1.f / (1.f + expf(-x)); }

// ---------------------------------------------------------------------------
// fp16 HMMA GEMM:  Ch[M, Ntot] = fp16( A[M,256] @ Wt^T + bias )
//   CTA tile 128x128, 8 warps (2m x 4n), warp 64x32, k-chunk 64 x4,
//   3-stage cp.async pipeline, one barrier per chunk, 96KB smem, 2 CTAs/SM.
// ---------------------------------------------------------------------------
#define STG    32768
#define OA     0
#define OBH    16384
#define GSMEM  (3 * STG)   // 98304 bytes

__global__ void __launch_bounds__(256, 2)
gemm_f16(const __half* __restrict__ A,
         const __half* __restrict__ Bhi,
         const float* __restrict__ bias,
         __half* __restrict__ Ch,
         int M, int Ntot)
{
    extern __shared__ char smem[];
    const uint32_t sb = s2u(smem);
    const int tid  = threadIdx.x;
    const int lane = tid & 31;
    const int wid  = tid >> 5;
    const int wm   = wid & 1;
    const int wn   = wid >> 1;
    const int bm   = blockIdx.x * 128;
    const int n0   = blockIdx.y * 128;

    float acc[4][4][4];
    #pragma unroll
    for (int a = 0; a < 4; a++)
        #pragma unroll
        for (int b = 0; b < 4; b++)
            #pragma unroll
            for (int c = 0; c < 4; c++) acc[a][b][c] = 0.f;

    auto stage_chunk = [&](int kc) {
        uint32_t sa = sb + (kc % 3) * STG;
        #pragma unroll
        for (int t = 0; t < 4; t++) {
            int i = tid + t * 256;
            int row = i >> 3, g = i & 7;
            uint32_t d = row * 128 + ((g ^ (row & 7)) << 4);
            int  arow = bm + row;
            int  av   = arow < M ? 16 : 0;
            size_t as = (size_t)(arow < M ? arow : 0) * 256 + kc * 64 + g * 8;
            size_t bs = (size_t)(n0 + row) * 256 + kc * 64 + g * 8;
            cpa16(sa + OA  + d, A + as, av);
            cpa16(sa + OBH + d, Bhi + bs, 16);
        }
        cpa_commit();
    };

    stage_chunk(0);
    stage_chunk(1);

    for (int kc = 0; kc < 4; kc++) {
        if (kc < 3)
            asm volatile("cp.async.wait_group 1;" ::: "memory");
        else
            asm volatile("cp.async.wait_group 0;" ::: "memory");
        __syncthreads();
        if (kc + 2 < 4) stage_chunk(kc + 2);

        const uint32_t sa = sb + (kc % 3) * STG;
        #pragma unroll
        for (int ks = 0; ks < 4; ks++) {
            uint32_t af[4][4], bh[2][4];
            #pragma unroll
            for (int mi = 0; mi < 4; mi++) {
                int rA = wm * 64 + mi * 16 + (lane & 15);
                int gA = 2 * ks + (lane >> 4);
                ldm4(af[mi], swadr(sa + OA, rA, gA));
            }
            #pragma unroll
            for (int bi = 0; bi < 2; bi++) {
                int rB = wn * 32 + bi * 16 + (lane & 7) + ((lane >> 4) << 3);
                int gB = 2 * ks + ((lane >> 3) & 1);
                ldm4(bh[bi], swadr(sa + OBH, rB, gB));
            }
            #pragma unroll
            for (int mi = 0; mi < 4; mi++)
                #pragma unroll
                for (int nf = 0; nf < 4; nf++)
                    mma16816(acc[mi][nf], af[mi], &bh[nf >> 1][(nf & 1) * 2]);
        }
    }

    #pragma unroll
    for (int mi = 0; mi < 4; mi++) {
        #pragma unroll
        for (int nf = 0; nf < 4; nf++) {
            int r0  = bm + wm * 64 + mi * 16 + (lane >> 2);
            int col = n0 + wn * 32 + nf * 8 + ((lane & 3) << 1);
            float2 b2 = *(const float2*)&bias[col];
            if (r0 < M) {
                size_t o = (size_t)r0 * Ntot + col;
                *(uint32_t*)&Ch[o] = packh(__float2half_rn(acc[mi][nf][0] + b2.x),
                                           __float2half_rn(acc[mi][nf][1] + b2.y));
            }
            if (r0 + 8 < M) {
                size_t o = (size_t)(r0 + 8) * Ntot + col;
                *(uint32_t*)&Ch[o] = packh(__float2half_rn(acc[mi][nf][2] + b2.x),
                                           __float2half_rn(acc[mi][nf][3] + b2.y));
            }
        }
    }
}

// ---------------------------------------------------------------------------
// Combined weight prep: one launch transposes all 8 matrices -> fp16 rows.
// ---------------------------------------------------------------------------
struct PrepArgs {
    const float* W[8];
    int N[8];
    int row_off[8];
    int blk_cum[9];
};

__global__ void prep_all(PrepArgs pa, __half* __restrict__ wthi)
{
    __shared__ float tile[256][33];
    int b = blockIdx.x;
    int m = 0;
    while (b >= pa.blk_cum[m + 1]) m++;
    const int n0 = (b - pa.blk_cum[m]) * 32;
    const float* W = pa.W[m];
    const int N = pa.N[m];
    __half* out = wthi + (size_t)pa.row_off[m] * 256;

    const int tx = threadIdx.x & 31;
    const int ty = threadIdx.x >> 5;
    for (int k = ty; k < 256; k += 8)
        tile[k][tx] = W[(size_t)k * N + n0 + tx];
    __syncthreads();
    for (int nr = ty * 4; nr < ty * 4 + 4; nr++)
        for (int k = tx; k < 256; k += 32)
            out[(size_t)(n0 + nr) * 256 + k] = __float2half_rn(tile[k][nr]);
}

__global__ void split_x(const float* __restrict__ x,
                        __half* __restrict__ xh, int total4)
{
    int i = blockIdx.x * blockDim.x + threadIdx.x;
    if (i >= total4) return;
    float4 v = *(const float4*)&x[i * 4];
    uint2 p;
    p.x = packh(__float2half_rn(v.x), __float2half_rn(v.y));
    p.y = packh(__float2half_rn(v.z), __float2half_rn(v.w));
    *(uint2*)&xh[i * 4] = p;
}

// bcomb[c] = (bl @ U)[c] + Ub[c]   (fp32, 1024 outputs)
__global__ void bcomb_kernel(const float* __restrict__ bl_,
                             const float* __restrict__ Uiou_w,
                             const float* __restrict__ Uiou_b,
                             const float* __restrict__ Uf_w,
                             const float* __restrict__ Uf_b,
                             float* __restrict__ out)
{
    int c = blockIdx.x * 256 + threadIdx.x;   // 0..1023
    float acc;
    if (c < 768) {
        acc = Uiou_b[c];
        for (int j = 0; j < 256; j++) acc += bl_[j] * Uiou_w[(size_t)j * 768 + c];
    } else {
        int c2 = c - 768;
        acc = Uf_b[c2];
        for (int j = 0; j < 256; j++) acc += bl_[j] * Uf_w[(size_t)j * 256 + c2];
    }
    out[c] = acc;
}

// ---------------------------------------------------------------------------
// Attention: one block per node, warp per head
// ---------------------------------------------------------------------------
__global__ void attn_kernel(const __half* __restrict__ xfq,
                            const __half* __restrict__ kkvv,
                            __half* __restrict__ out,
                            int s0)
{
    const int node = blockIdx.x;
    const int d = threadIdx.x;
    const float qv = __half2float(xfq[(size_t)(s0 + node) * 512 + 256 + d]);

    float logit[4];
    #pragma unroll
    for (int k = 0; k < 4; k++) {
        float p = qv * __half2float(kkvv[((size_t)(node * 4 + k)) * 512 + d]);
        #pragma unroll
        for (int off = 16; off > 0; off >>= 1)
            p += __shfl_xor_sync(0xffffffffu, p, off);
        logit[k] = p * 0.1767766952966369f;
    }
    float mx = fmaxf(fmaxf(logit[0], logit[1]), fmaxf(logit[2], logit[3]));
    float e[4], s = 0.f;
    #pragma unroll
    for (int k = 0; k < 4; k++) { e[k] = expf(logit[k] - mx); s += e[k]; }
    const float inv = 1.f / s;

    float o = 0.f;
    #pragma unroll
    for (int k = 0; k < 4; k++)
        o += (e[k] * inv) * __half2float(kkvv[((size_t)(node * 4 + k)) * 512 + 256 + d]);
    out[(size_t)node * 256 + d] = __float2half_rn(o);
}

// ---------------------------------------------------------------------------
// Elementwise
// ---------------------------------------------------------------------------
__device__ __forceinline__ float h2f(const __half h) { return __half2float(h); }

__global__ void leaf_kernel(const __half* __restrict__ xiou,
                            float* __restrict__ h_out,
                            float* __restrict__ c_out,
                            __half* __restrict__ hh)
{
    const size_t node = LEAF_S + (size_t)blockIdx.x * 4 + (threadIdx.x >> 6);
    const int j = (threadIdx.x & 63) << 2;
    const __half2* pi = (const __half2*)&xiou[node * 768 + j];
    const __half2* po = (const __half2*)&xiou[node * 768 + 256 + j];
    const __half2* pu = (const __half2*)&xiou[node * 768 + 512 + j];
    float2 ia = __half22float2(pi[0]), ib = __half22float2(pi[1]);
    float2 oa = __half22float2(po[0]), ob = __half22float2(po[1]);
    float2 ua = __half22float2(pu[0]), ub = __half22float2(pu[1]);
    float4 c, h;
    c.x = sigm(ia.x) * tanhf(ua.x); h.x = sigm(oa.x) * tanhf(c.x);
    c.y = sigm(ia.y) * tanhf(ua.y); h.y = sigm(oa.y) * tanhf(c.y);
    c.z = sigm(ib.x) * tanhf(ub.x); h.z = sigm(ob.x) * tanhf(c.z);
    c.w = sigm(ib.y) * tanhf(ub.y); h.w = sigm(ob.y) * tanhf(c.w);
    *(float4*)&h_out[node * 256 + j] = h;
    *(float4*)&c_out[node * 256 + j] = c;
    uint2 p;
    p.x = packh(__float2half_rn(h.x), __float2half_rn(h.y));
    p.y = packh(__float2half_rn(h.z), __float2half_rn(h.w));
    *(uint2*)&hh[node * 256 + j] = p;
}

__global__ void combine_kernel(const __half* __restrict__ xiou,
                               const __half* __restrict__ xfq,
                               const __half* __restrict__ hu,
                               float* __restrict__ h_out,
                               float* __restrict__ c_out,
                               __half* __restrict__ hh,
                               int s0, int child_start)
{
    const int i = blockIdx.x;
    const int j = threadIdx.x;
    const size_t gr = (size_t)(s0 + i);

    const float ig = h2f(xiou[gr * 768 + j])       + h2f(hu[(size_t)i * 1024 + j]);
    const float og = h2f(xiou[gr * 768 + 256 + j]) + h2f(hu[(size_t)i * 1024 + 256 + j]);
    const float ug = h2f(xiou[gr * 768 + 512 + j]) + h2f(hu[(size_t)i * 1024 + 512 + j]);
    const float f  = sigm(h2f(xfq[gr * 512 + j])   + h2f(hu[(size_t)i * 1024 + 768 + j]));

    const size_t cb = (size_t)(child_start + i * 4) * 256 + j;
    const float csum = c_out[cb] + c_out[cb + 256] + c_out[cb + 512] + c_out[cb + 768];

    const float c = sigm(ig) * tanhf(ug) + f * csum;
    const float h = sigm(og) * tanhf(c);
    h_out[gr * 256 + j] = h;
    c_out[gr * 256 + j] = c;
    hh[gr * 256 + j] = __float2half_rn(h);
}

// ---------------------------------------------------------------------------
// Fused small-level kernel (n <= 1024): one CTA = 2 nodes, all phases fp32.
// ---------------------------------------------------------------------------
__global__ void __launch_bounds__(512, 1)
fused_level(const __half* __restrict__ xiou,
            const __half* __restrict__ xfq,
            const float* __restrict__ Wk,  const float* __restrict__ bk_,
            const float* __restrict__ Wv,  const float* __restrict__ bv_,
            const float* __restrict__ Wl,  const float* __restrict__ bl_,
            const float* __restrict__ Uiou_w, const float* __restrict__ Uiou_b,
            const float* __restrict__ Uf_w,   const float* __restrict__ Uf_b,
            float* __restrict__ h_out, float* __restrict__ c_out,
            __half* __restrict__ hh,
            int s0, int cs, int n)
{
    __shared__ float chs[8][256];
    __shared__ float kvs[8][512];
    __shared__ float atts[2][256];
    __shared__ float hatts[2][256];
    __shared__ float hus[2][1024];

    const int tid = threadIdx.x;
    const int node0 = blockIdx.x * 2;
    const int nn = (n - node0) < 2 ? (n - node0) : 2;

    for (int idx = tid; idx < 4 * nn * 256; idx += 512) {
        int r = idx >> 8, k = idx & 255;
        chs[r][k] = h_out[(size_t)(cs + node0 * 4 + r) * 256 + k];
    }
    __syncthreads();

    {
        int c = tid;
        const float* W = (c < 256) ? (Wk + c) : (Wv + (c - 256));
        float acc[8] = {0, 0, 0, 0, 0, 0, 0, 0};
        int rmax = 4 * nn;
        #pragma unroll 4
        for (int k = 0; k < 256; k++) {
            float w = W[(size_t)k * 256];
            #pragma unroll
            for (int r = 0; r < 8; r++)
                acc[r] += chs[r][k] * w;
        }
        float b = (c < 256) ? bk_[c] : bv_[c - 256];
        for (int r = 0; r < rmax; r++) kvs[r][c] = acc[r] + b;
    }
    __syncthreads();

    {
        int i = tid >> 8, d = tid & 255;
        if (i < nn) {
            float qv = h2f(xfq[(size_t)(s0 + node0 + i) * 512 + 256 + d]);
            float logit[4];
            #pragma unroll
            for (int k = 0; k < 4; k++) {
                float p = qv * kvs[i * 4 + k][d];
                #pragma unroll
                for (int off = 16; off > 0; off >>= 1)
                    p += __shfl_xor_sync(0xffffffffu, p, off);
                logit[k] = p * 0.1767766952966369f;
            }
            float mx = fmaxf(fmaxf(logit[0], logit[1]), fmaxf(logit[2], logit[3]));
            float e[4], s = 0.f;
            #pragma unroll
            for (int k = 0; k < 4; k++) { e[k] = expf(logit[k] - mx); s += e[k]; }
            float inv = 1.f / s;
            float o = 0.f;
            #pragma unroll
            for (int k = 0; k < 4; k++)
                o += (e[k] * inv) * kvs[i * 4 + k][256 + d];
            atts[i][d] = o;
        }
    }
    __syncthreads();

    if (tid < 256) {
        int c = tid;
        float a0 = 0.f, a1 = 0.f;
        #pragma unroll 4
        for (int k = 0; k < 256; k++) {
            float w = Wl[(size_t)k * 256 + c];
            a0 += atts[0][k] * w;
            a1 += atts[1][k] * w;
        }
        hatts[0][c] = a0 + bl_[c];
        hatts[1][c] = a1 + bl_[c];
    }
    __syncthreads();

    #pragma unroll
    for (int pass = 0; pass < 2; pass++) {
        int cc = tid + pass * 512;
        float a0 = 0.f, a1 = 0.f, b;
        if (cc < 768) {
            #pragma unroll 4
            for (int k = 0; k < 256; k++) {
                float w = Uiou_w[(size_t)k * 768 + cc];
                a0 += hatts[0][k] * w;
                a1 += hatts[1][k] * w;
            }
            b = Uiou_b[cc];
        } else {
            int c2 = cc - 768;
            #pragma unroll 4
            for (int k = 0; k < 256; k++) {
                float w = Uf_w[(size_t)k * 256 + c2];
                a0 += hatts[0][k] * w;
                a1 += hatts[1][k] * w;
            }
            b = Uf_b[c2];
        }
        hus[0][cc] = a0 + b;
        hus[1][cc] = a1 + b;
    }
    __syncthreads();

    {
        int i = tid >> 8, j = tid & 255;
        if (i < nn) {
            size_t g = (size_t)(s0 + node0 + i);
            float ig = h2f(xiou[g * 768 + j])       + hus[i][j];
            float og = h2f(xiou[g * 768 + 256 + j]) + hus[i][256 + j];
            float ug = h2f(xiou[g * 768 + 512 + j]) + hus[i][512 + j];
            float f  = sigm(h2f(xfq[g * 512 + j])   + hus[i][768 + j]);
            size_t cb = (size_t)(cs + (node0 + i) * 4) * 256 + j;
            float csum = c_out[cb] + c_out[cb + 256] + c_out[cb + 512] + c_out[cb + 768];
            float cv = sigm(ig) * tanhf(ug) + f * csum;
            float hv = sigm(og) * tanhf(cv);
            h_out[g * 256 + j] = hv;
            c_out[g * 256 + j] = cv;
            hh[g * 256 + j] = __float2half_rn(hv);
        }
    }
}

// ---------------------------------------------------------------------------
// Launch
// ---------------------------------------------------------------------------
extern "C" void kernel_launch(void* const* d_in, const int* in_sizes, int n_in,
                              void* d_out, int out_size)
{
    const float* x      = (const float*)d_in[0];
    const float* W_iou  = (const float*)d_in[1];
    const float* b_iou  = (const float*)d_in[2];
    const float* W_f    = (const float*)d_in[3];
    const float* b_f    = (const float*)d_in[4];
    const float* Wq     = (const float*)d_in[5];
    const float* bq     = (const float*)d_in[6];
    const float* Wk     = (const float*)d_in[7];
    const float* bk     = (const float*)d_in[8];
    const float* Wv     = (const float*)d_in[9];
    const float* bv     = (const float*)d_in[10];
    const float* Wl     = (const float*)d_in[11];
    const float* bl     = (const float*)d_in[12];
    const float* Uiou_w = (const float*)d_in[13];
    const float* Uiou_b = (const float*)d_in[14];
    const float* Uf_w   = (const float*)d_in[15];
    const float* Uf_b   = (const float*)d_in[16];

    float* h_out = (float*)d_out;
    float* c_out = h_out + (size_t)NN * 256;

    float *bias, *bcomb, *zbias;
    __half *xiou, *xfq, *hu, *kkvv, *att, *xh, *hh, *wthi, *wcombt, *wlplain;
    cudaGetSymbolAddress((void**)&xiou,    g_xiou);
    cudaGetSymbolAddress((void**)&xfq,     g_xfq);
    cudaGetSymbolAddress((void**)&hu,      g_hu);
    cudaGetSymbolAddress((void**)&bias,    g_bias);
    cudaGetSymbolAddress((void**)&bcomb,   g_bcomb);
    cudaGetSymbolAddress((void**)&zbias,   g_zbias);
    cudaGetSymbolAddress((void**)&kkvv,    g_kkvv);
    cudaGetSymbolAddress((void**)&att,     g_att);
    cudaGetSymbolAddress((void**)&xh,      g_xh);
    cudaGetSymbolAddress((void**)&hh,      g_hh);
    cudaGetSymbolAddress((void**)&wthi,    g_wthi);
    cudaGetSymbolAddress((void**)&wcombt,  g_wcombt);
    cudaGetSymbolAddress((void**)&wlplain, g_wlplain);

    cudaFuncSetAttribute(gemm_f16, cudaFuncAttributeMaxDynamicSharedMemorySize, GSMEM);

    auto GEMMB = [&](const __half* A, const __half* Brow, const float* bias_,
                     __half* Ch, int M, int Ntot) {
        dim3 grid((M + 127) / 128, Ntot / 128);
        gemm_f16<<<grid, 256, GSMEM>>>(A, Brow, bias_, Ch, M, Ntot);
    };
    auto GEMM = [&](const __half* A, int wt, __half* Ch, int M, int Ntot) {
        GEMMB(A, wthi + (size_t)wt * 256, bias + wt, Ch, M, Ntot);
    };

    // ---- combined weight prep (1 launch) ----
    PrepArgs pa;
    pa.W[0] = W_iou;  pa.N[0] = 768; pa.row_off[0] = WT_IOU;
    pa.W[1] = W_f;    pa.N[1] = 256; pa.row_off[1] = WT_FQ;
    pa.W[2] = Wq;     pa.N[2] = 256; pa.row_off[2] = WT_FQ + 256;
    pa.W[3] = Wk;     pa.N[3] = 256; pa.row_off[3] = WT_KV;
    pa.W[4] = Wv;     pa.N[4] = 256; pa.row_off[4] = WT_KV + 256;
    pa.W[5] = Wl;     pa.N[5] = 256; pa.row_off[5] = WT_L;
    pa.W[6] = Uiou_w; pa.N[6] = 768; pa.row_off[6] = WT_U;
    pa.W[7] = Uf_w;   pa.N[7] = 256; pa.row_off[7] = WT_U + 768;
    pa.blk_cum[0] = 0;
    for (int m = 0; m < 8; m++) pa.blk_cum[m + 1] = pa.blk_cum[m] + pa.N[m] / 32;
    prep_all<<<pa.blk_cum[8], 256>>>(pa, wthi);

    // ---- bias concat ----
    cudaMemcpyAsync(bias + WT_IOU,      b_iou,  768 * 4, cudaMemcpyDeviceToDevice, 0);
    cudaMemcpyAsync(bias + WT_FQ,       b_f,    256 * 4, cudaMemcpyDeviceToDevice, 0);
    cudaMemcpyAsync(bias + WT_FQ + 256, bq,     256 * 4, cudaMemcpyDeviceToDevice, 0);
    cudaMemcpyAsync(bias + WT_KV,       bk,     256 * 4, cudaMemcpyDeviceToDevice, 0);
    cudaMemcpyAsync(bias + WT_KV + 256, bv,     256 * 4, cudaMemcpyDeviceToDevice, 0);

    // ---- fold Wl into U:  wcombt[c,k] = sum_j U[j,c] * Wl[k,j]  (fp16) ----
    split_x<<<(256 * 256 / 4 + 255) / 256, 256>>>(Wl, wlplain, 256 * 256 / 4);
    GEMMB(wthi + (size_t)WT_U * 256, wlplain, zbias, wcombt, 1024, 256);
    bcomb_kernel<<<4, 256>>>(bl, Uiou_w, Uiou_b, Uf_w, Uf_b, bcomb);

    // ---- split x, precompute GEMMs ----
    const int tot4 = NN * 256 / 4;
    split_x<<<(tot4 + 255) / 256, 256>>>(x, xh, tot4);
    GEMM(xh, WT_IOU, xiou, NN, 768);
    GEMM(xh, WT_FQ,  xfq,  NI, 512);

    // ---- leaf level ----
    leaf_kernel<<<LEAF_N / 4, 256>>>(xiou, h_out, c_out, hh);

    // ---- internal levels, bottom-up ----
    const int starts[9] = {0, 1, 5, 21, 85, 341, 1365, 5461, 21845};
    for (int l = 7; l >= 6; l--) {
        const int n  = 1 << (2 * l);
        const int s0 = starts[l];
        const int cs = starts[l + 1];
        const int nK = n * 4;
        const __half* chh = hh + (size_t)cs * 256;

        GEMM(chh, WT_KV, kkvv, nK, 512);
        attn_kernel<<<n, 256>>>(xfq, kkvv, att, s0);
        GEMMB(att, wcombt, bcomb, hu, n, 1024);     // folded Wl+U
        combine_kernel<<<n, 256>>>(xiou, xfq, hu, h_out, c_out, hh, s0, cs);
    }
    for (int l = 5; l >= 0; l--) {
        const int n  = 1 << (2 * l);
        fused_level<<<(n + 1) / 2, 512>>>(xiou, xfq,
                                          Wk, bk, Wv, bv, Wl, bl,
                                          Uiou_w, Uiou_b, Uf_w, Uf_b,
                                          h_out, c_out, hh,
                                          starts[l], starts[l + 1], n);
    }
}

// round 16
// speedup vs baseline: 1.0555x; 1.0555x over previous
#include <cuda_runtime.h>
#include <cuda_fp16.h>
#include <math.h>
#include <stdint.h>

// ---------------------------------------------------------------------------
// Problem constants
// ---------------------------------------------------------------------------
#define NN        87381     // total nodes = (4^9-1)/3
#define NI        21845     // internal nodes
#define LEAF_N    65536
#define LEAF_S    21845

// ---------------------------------------------------------------------------
// Device scratch (static — no allocation allowed)
// ---------------------------------------------------------------------------
__device__ __half g_xiou[NN * 768];          // iou preactivations (fp16)
__device__ __half g_xfq[NI * 512];           // cols 0-255: x_f, 256-511: q
__device__ __half g_hu[16384 * 1024];        // cols 0-767: h_iou, 768-1023: h_f
__device__ __half g_kkvv[65536 * 512];       // cols 0-255: k, 256-511: v
__device__ __half g_att[16384 * 256];
__device__ __half g_xh[NN * 256];            // x as fp16
__device__ __half g_hh[NN * 256];            // h as fp16

// weight rows (transposed fp16). row index == bias index.
#define WT_IOU  0       // 768 rows
#define WT_FQ   768     // 512 rows (f, q)
#define WT_KV   1280    // 512 rows (k, v)
#define WT_L    1792    // 256 rows (source for fold)
#define WT_U    2048    // 1024 rows (uiou, uf) — source for fold
__device__ __half g_wthi[3072 * 256];
__device__ float  g_bias[3072];

// folded Wl*U weights: 1024 rows x 256 k (fp16), fused bias, plain-Wl fp16
__device__ __half g_wcombt[1024 * 256];
__device__ float  g_bcomb[1024];
__device__ __half g_wlplain[256 * 256];
__device__ float  g_zbias[256];              // zero-initialized by CUDA

// ---------------------------------------------------------------------------
// PTX helpers (sm_80+ — safe for plain sm_103 ptxas target)
// ---------------------------------------------------------------------------
__device__ __forceinline__ uint32_t s2u(const void* p) {
    uint32_t a;
    asm("{ .reg .u64 t; cvta.to.shared.u64 t, %1; cvt.u32.u64 %0, t; }"
        : "=r"(a) : "l"(p));
    return a;
}
__device__ __forceinline__ void cpa16(uint32_t dst, const void* src, int nbytes) {
    asm volatile("cp.async.cg.shared.global [%0], [%1], 16, %2;"
                 :: "r"(dst), "l"(src), "r"(nbytes) : "memory");
}
__device__ __forceinline__ void cpa_commit() {
    asm volatile("cp.async.commit_group;" ::: "memory");
}
__device__ __forceinline__ void ldm4(uint32_t* r, uint32_t addr) {
    asm volatile("ldmatrix.sync.aligned.m8n8.x4.shared.b16 {%0,%1,%2,%3}, [%4];"
                 : "=r"(r[0]), "=r"(r[1]), "=r"(r[2]), "=r"(r[3]) : "r"(addr));
}
__device__ __forceinline__ void mma16816(float* c, const uint32_t* a, const uint32_t* b) {
    asm volatile(
        "mma.sync.aligned.m16n8k16.row.col.f32.f16.f16.f32 "
        "{%0,%1,%2,%3}, {%4,%5,%6,%7}, {%8,%9}, {%0,%1,%2,%3};"
        : "+f"(c[0]), "+f"(c[1]), "+f"(c[2]), "+f"(c[3])
        : "r"(a[0]), "r"(a[1]), "r"(a[2]), "r"(a[3]), "r"(b[0]), "r"(b[1]));
}
__device__ __forceinline__ uint32_t swadr(uint32_t base, int row, int gran) {
    return base + row * 128 + ((gran ^ (row & 7)) << 4);
}
__device__ __forceinline__ uint32_t packh(__half a, __half b) {
    return ((uint32_t)__half_as_ushort(b) << 16) | __half_as_ushort(a);
}
__device__ __forceinline__ float sigm(float x) { return 1.f / (1.f + expf(-x)); }

// ---------------------------------------------------------------------------
// fp16 HMMA GEMM (WIDE):  Ch[M, Ntot] = fp16( A[M,256] @ Wt^T + bias )
//   CTA tile 128x256, 8 warps (2m x 4n), warp tile 64x64 (16 MAC/byte of
//   smem traffic — balances HMMA rate vs 128B/cyc smem), k-chunk 64 x4,
//   3-stage cp.async, barrier-before-stage (race-free), 1 CTA/SM (reg-bound).
// ---------------------------------------------------------------------------
#define STG    49152            // 16KB A + 32KB B per stage
#define OA     0
#define OB     16384
#define GSMEM  (3 * STG)        // 147456 bytes

__global__ void __launch_bounds__(256)
gemm_f16(const __half* __restrict__ A,
         const __half* __restrict__ Bhi,
         const float* __restrict__ bias,
         __half* __restrict__ Ch,
         int M, int Ntot)
{
    extern __shared__ char smem[];
    const uint32_t sb = s2u(smem);
    const int tid  = threadIdx.x;
    const int lane = tid & 31;
    const int wid  = tid >> 5;
    const int wm   = wid & 1;       // 2 m-warps
    const int wn   = wid >> 1;      // 4 n-warps
    const int bm   = blockIdx.x * 128;
    const int n0   = blockIdx.y * 256;

    float acc[4][8][4];
    #pragma unroll
    for (int a = 0; a < 4; a++)
        #pragma unroll
        for (int b = 0; b < 8; b++)
            #pragma unroll
            for (int c = 0; c < 4; c++) acc[a][b][c] = 0.f;

    auto stage_chunk = [&](int kc) {
        uint32_t sa = sb + (kc % 3) * STG;
        // A: 1024 16B-slots, B: 2048 slots -> 12 per thread
        #pragma unroll
        for (int t = 0; t < 4; t++) {           // A
            int i = tid + t * 256;
            int row = i >> 3, g = i & 7;
            uint32_t d = row * 128 + ((g ^ (row & 7)) << 4);
            int  arow = bm + row;
            int  av   = arow < M ? 16 : 0;
            size_t as = (size_t)(arow < M ? arow : 0) * 256 + kc * 64 + g * 8;
            cpa16(sa + OA + d, A + as, av);
        }
        #pragma unroll
        for (int t = 0; t < 8; t++) {           // B (256 rows)
            int i = tid + t * 256;
            int row = i >> 3, g = i & 7;
            uint32_t d = row * 128 + ((g ^ (row & 7)) << 4);
            size_t bs = (size_t)(n0 + row) * 256 + kc * 64 + g * 8;
            cpa16(sa + OB + d, Bhi + bs, 16);
        }
        cpa_commit();
    };

    stage_chunk(0);
    stage_chunk(1);

    for (int kc = 0; kc < 4; kc++) {
        if (kc < 3)
            asm volatile("cp.async.wait_group 1;" ::: "memory");
        else
            asm volatile("cp.async.wait_group 0;" ::: "memory");
        __syncthreads();                 // everyone done with chunk kc-1
        if (kc + 2 < 4) stage_chunk(kc + 2);

        const uint32_t sa = sb + (kc % 3) * STG;
        #pragma unroll
        for (int ks = 0; ks < 4; ks++) {
            uint32_t af[4][4], bh[4][4];
            #pragma unroll
            for (int mi = 0; mi < 4; mi++) {
                int rA = wm * 64 + mi * 16 + (lane & 15);
                int gA = 2 * ks + (lane >> 4);
                ldm4(af[mi], swadr(sa + OA, rA, gA));
            }
            #pragma unroll
            for (int bi = 0; bi < 4; bi++) {
                int rB = wn * 64 + bi * 16 + (lane & 7) + ((lane >> 4) << 3);
                int gB = 2 * ks + ((lane >> 3) & 1);
                ldm4(bh[bi], swadr(sa + OB, rB, gB));
            }
            #pragma unroll
            for (int mi = 0; mi < 4; mi++)
                #pragma unroll
                for (int nf = 0; nf < 8; nf++)
                    mma16816(acc[mi][nf], af[mi], &bh[nf >> 1][(nf & 1) * 2]);
        }
    }

    #pragma unroll
    for (int mi = 0; mi < 4; mi++) {
        #pragma unroll
        for (int nf = 0; nf < 8; nf++) {
            int r0  = bm + wm * 64 + mi * 16 + (lane >> 2);
            int col = n0 + wn * 64 + nf * 8 + ((lane & 3) << 1);
            float2 b2 = *(const float2*)&bias[col];
            if (r0 < M) {
                size_t o = (size_t)r0 * Ntot + col;
                *(uint32_t*)&Ch[o] = packh(__float2half_rn(acc[mi][nf][0] + b2.x),
                                           __float2half_rn(acc[mi][nf][1] + b2.y));
            }
            if (r0 + 8 < M) {
                size_t o = (size_t)(r0 + 8) * Ntot + col;
                *(uint32_t*)&Ch[o] = packh(__float2half_rn(acc[mi][nf][2] + b2.x),
                                           __float2half_rn(acc[mi][nf][3] + b2.y));
            }
        }
    }
}

// ---------------------------------------------------------------------------
// Combined weight prep: one launch transposes all 8 matrices -> fp16 rows.
// ---------------------------------------------------------------------------
struct PrepArgs {
    const float* W[8];
    int N[8];
    int row_off[8];
    int blk_cum[9];
};

__global__ void prep_all(PrepArgs pa, __half* __restrict__ wthi)
{
    __shared__ float tile[256][33];
    int b = blockIdx.x;
    int m = 0;
    while (b >= pa.blk_cum[m + 1]) m++;
    const int n0 = (b - pa.blk_cum[m]) * 32;
    const float* W = pa.W[m];
    const int N = pa.N[m];
    __half* out = wthi + (size_t)pa.row_off[m] * 256;

    const int tx = threadIdx.x & 31;
    const int ty = threadIdx.x >> 5;
    for (int k = ty; k < 256; k += 8)
        tile[k][tx] = W[(size_t)k * N + n0 + tx];
    __syncthreads();
    for (int nr = ty * 4; nr < ty * 4 + 4; nr++)
        for (int k = tx; k < 256; k += 32)
            out[(size_t)(n0 + nr) * 256 + k] = __float2half_rn(tile[k][nr]);
}

__global__ void split_x(const float* __restrict__ x,
                        __half* __restrict__ xh, int total4)
{
    int i = blockIdx.x * blockDim.x + threadIdx.x;
    if (i >= total4) return;
    float4 v = *(const float4*)&x[i * 4];
    uint2 p;
    p.x = packh(__float2half_rn(v.x), __float2half_rn(v.y));
    p.y = packh(__float2half_rn(v.z), __float2half_rn(v.w));
    *(uint2*)&xh[i * 4] = p;
}

// bcomb[c] = (bl @ U)[c] + Ub[c]; 32 blocks, each 32 outputs, 8-way j-split.
__global__ void bcomb_kernel(const float* __restrict__ bl_,
                             const float* __restrict__ Uiou_w,
                             const float* __restrict__ Uiou_b,
                             const float* __restrict__ Uf_w,
                             const float* __restrict__ Uf_b,
                             float* __restrict__ out)
{
    __shared__ float partial[8][32];
    const int c  = blockIdx.x * 32 + (threadIdx.x & 31);   // 0..1023
    const int jg = threadIdx.x >> 5;                       // 0..7
    float acc = 0.f;
    if (c < 768) {
        for (int j = jg * 32; j < jg * 32 + 32; j++)
            acc += bl_[j] * Uiou_w[(size_t)j * 768 + c];
    } else {
        int c2 = c - 768;
        for (int j = jg * 32; j < jg * 32 + 32; j++)
            acc += bl_[j] * Uf_w[(size_t)j * 256 + c2];
    }
    partial[jg][threadIdx.x & 31] = acc;
    __syncthreads();
    if (threadIdx.x < 32) {
        int cc = blockIdx.x * 32 + threadIdx.x;
        float s = (cc < 768) ? Uiou_b[cc] : Uf_b[cc - 768];
        #pragma unroll
        for (int g = 0; g < 8; g++) s += partial[g][threadIdx.x];
        out[cc] = s;
    }
}

// ---------------------------------------------------------------------------
// Attention: one block per node, warp per head
// ---------------------------------------------------------------------------
__global__ void attn_kernel(const __half* __restrict__ xfq,
                            const __half* __restrict__ kkvv,
                            __half* __restrict__ out,
                            int s0)
{
    const int node = blockIdx.x;
    const int d = threadIdx.x;
    const float qv = __half2float(xfq[(size_t)(s0 + node) * 512 + 256 + d]);

    float logit[4];
    #pragma unroll
    for (int k = 0; k < 4; k++) {
        float p = qv * __half2float(kkvv[((size_t)(node * 4 + k)) * 512 + d]);
        #pragma unroll
        for (int off = 16; off > 0; off >>= 1)
            p += __shfl_xor_sync(0xffffffffu, p, off);
        logit[k] = p * 0.1767766952966369f;
    }
    float mx = fmaxf(fmaxf(logit[0], logit[1]), fmaxf(logit[2], logit[3]));
    float e[4], s = 0.f;
    #pragma unroll
    for (int k = 0; k < 4; k++) { e[k] = expf(logit[k] - mx); s += e[k]; }
    const float inv = 1.f / s;

    float o = 0.f;
    #pragma unroll
    for (int k = 0; k < 4; k++)
        o += (e[k] * inv) * __half2float(kkvv[((size_t)(node * 4 + k)) * 512 + 256 + d]);
    out[(size_t)node * 256 + d] = __float2half_rn(o);
}

// ---------------------------------------------------------------------------
// Elementwise
// ---------------------------------------------------------------------------
__device__ __forceinline__ float h2f(const __half h) { return __half2float(h); }

__global__ void leaf_kernel(const __half* __restrict__ xiou,
                            float* __restrict__ h_out,
                            float* __restrict__ c_out,
                            __half* __restrict__ hh)
{
    const size_t node = LEAF_S + (size_t)blockIdx.x * 4 + (threadIdx.x >> 6);
    const int j = (threadIdx.x & 63) << 2;
    const __half2* pi = (const __half2*)&xiou[node * 768 + j];
    const __half2* po = (const __half2*)&xiou[node * 768 + 256 + j];
    const __half2* pu = (const __half2*)&xiou[node * 768 + 512 + j];
    float2 ia = __half22float2(pi[0]), ib = __half22float2(pi[1]);
    float2 oa = __half22float2(po[0]), ob = __half22float2(po[1]);
    float2 ua = __half22float2(pu[0]), ub = __half22float2(pu[1]);
    float4 c, h;
    c.x = sigm(ia.x) * tanhf(ua.x); h.x = sigm(oa.x) * tanhf(c.x);
    c.y = sigm(ia.y) * tanhf(ua.y); h.y = sigm(oa.y) * tanhf(c.y);
    c.z = sigm(ib.x) * tanhf(ub.x); h.z = sigm(ob.x) * tanhf(c.z);
    c.w = sigm(ib.y) * tanhf(ub.y); h.w = sigm(ob.y) * tanhf(c.w);
    *(float4*)&h_out[node * 256 + j] = h;
    *(float4*)&c_out[node * 256 + j] = c;
    uint2 p;
    p.x = packh(__float2half_rn(h.x), __float2half_rn(h.y));
    p.y = packh(__float2half_rn(h.z), __float2half_rn(h.w));
    *(uint2*)&hh[node * 256 + j] = p;
}

__global__ void combine_kernel(const __half* __restrict__ xiou,
                               const __half* __restrict__ xfq,
                               const __half* __restrict__ hu,
                               float* __restrict__ h_out,
                               float* __restrict__ c_out,
                               __half* __restrict__ hh,
                               int s0, int child_start)
{
    const int i = blockIdx.x;
    const int j = threadIdx.x;
    const size_t gr = (size_t)(s0 + i);

    const float ig = h2f(xiou[gr * 768 + j])       + h2f(hu[(size_t)i * 1024 + j]);
    const float og = h2f(xiou[gr * 768 + 256 + j]) + h2f(hu[(size_t)i * 1024 + 256 + j]);
    const float ug = h2f(xiou[gr * 768 + 512 + j]) + h2f(hu[(size_t)i * 1024 + 512 + j]);
    const float f  = sigm(h2f(xfq[gr * 512 + j])   + h2f(hu[(size_t)i * 1024 + 768 + j]));

    const size_t cb = (size_t)(child_start + i * 4) * 256 + j;
    const float csum = c_out[cb] + c_out[cb + 256] + c_out[cb + 512] + c_out[cb + 768];

    const float c = sigm(ig) * tanhf(ug) + f * csum;
    const float h = sigm(og) * tanhf(c);
    h_out[gr * 256 + j] = h;
    c_out[gr * 256 + j] = c;
    hh[gr * 256 + j] = __float2half_rn(h);
}

// ---------------------------------------------------------------------------
// Fused small-level kernel (n <= 64): one CTA = 2 nodes, all phases fp32.
// ---------------------------------------------------------------------------
__global__ void __launch_bounds__(512, 1)
fused_level(const __half* __restrict__ xiou,
            const __half* __restrict__ xfq,
            const float* __restrict__ Wk,  const float* __restrict__ bk_,
            const float* __restrict__ Wv,  const float* __restrict__ bv_,
            const float* __restrict__ Wl,  const float* __restrict__ bl_,
            const float* __restrict__ Uiou_w, const float* __restrict__ Uiou_b,
            const float* __restrict__ Uf_w,   const float* __restrict__ Uf_b,
            float* __restrict__ h_out, float* __restrict__ c_out,
            int s0, int cs, int n)
{
    __shared__ float chs[8][256];
    __shared__ float kvs[8][512];
    __shared__ float atts[2][256];
    __shared__ float hatts[2][256];
    __shared__ float hus[2][1024];

    const int tid = threadIdx.x;
    const int node0 = blockIdx.x * 2;
    const int nn = (n - node0) < 2 ? (n - node0) : 2;

    for (int idx = tid; idx < 4 * nn * 256; idx += 512) {
        int r = idx >> 8, k = idx & 255;
        chs[r][k] = h_out[(size_t)(cs + node0 * 4 + r) * 256 + k];
    }
    __syncthreads();

    {
        int c = tid;
        const float* W = (c < 256) ? (Wk + c) : (Wv + (c - 256));
        float acc[8] = {0, 0, 0, 0, 0, 0, 0, 0};
        int rmax = 4 * nn;
        #pragma unroll 4
        for (int k = 0; k < 256; k++) {
            float w = W[(size_t)k * 256];
            #pragma unroll
            for (int r = 0; r < 8; r++)
                acc[r] += chs[r][k] * w;
        }
        float b = (c < 256) ? bk_[c] : bv_[c - 256];
        for (int r = 0; r < rmax; r++) kvs[r][c] = acc[r] + b;
    }
    __syncthreads();

    {
        int i = tid >> 8, d = tid & 255;
        if (i < nn) {
            float qv = h2f(xfq[(size_t)(s0 + node0 + i) * 512 + 256 + d]);
            float logit[4];
            #pragma unroll
            for (int k = 0; k < 4; k++) {
                float p = qv * kvs[i * 4 + k][d];
                #pragma unroll
                for (int off = 16; off > 0; off >>= 1)
                    p += __shfl_xor_sync(0xffffffffu, p, off);
                logit[k] = p * 0.1767766952966369f;
            }
            float mx = fmaxf(fmaxf(logit[0], logit[1]), fmaxf(logit[2], logit[3]));
            float e[4], s = 0.f;
            #pragma unroll
            for (int k = 0; k < 4; k++) { e[k] = expf(logit[k] - mx); s += e[k]; }
            float inv = 1.f / s;
            float o = 0.f;
            #pragma unroll
            for (int k = 0; k < 4; k++)
                o += (e[k] * inv) * kvs[i * 4 + k][256 + d];
            atts[i][d] = o;
        }
    }
    __syncthreads();

    if (tid < 256) {
        int c = tid;
        float a0 = 0.f, a1 = 0.f;
        #pragma unroll 4
        for (int k = 0; k < 256; k++) {
            float w = Wl[(size_t)k * 256 + c];
            a0 += atts[0][k] * w;
            a1 += atts[1][k] * w;
        }
        hatts[0][c] = a0 + bl_[c];
        hatts[1][c] = a1 + bl_[c];
    }
    __syncthreads();

    #pragma unroll
    for (int pass = 0; pass < 2; pass++) {
        int cc = tid + pass * 512;
        float a0 = 0.f, a1 = 0.f, b;
        if (cc < 768) {
            #pragma unroll 4
            for (int k = 0; k < 256; k++) {
                float w = Uiou_w[(size_t)k * 768 + cc];
                a0 += hatts[0][k] * w;
                a1 += hatts[1][k] * w;
            }
            b = Uiou_b[cc];
        } else {
            int c2 = cc - 768;
            #pragma unroll 4
            for (int k = 0; k < 256; k++) {
                float w = Uf_w[(size_t)k * 256 + c2];
                a0 += hatts[0][k] * w;
                a1 += hatts[1][k] * w;
            }
            b = Uf_b[c2];
        }
        hus[0][cc] = a0 + b;
        hus[1][cc] = a1 + b;
    }
    __syncthreads();

    {
        int i = tid >> 8, j = tid & 255;
        if (i < nn) {
            size_t g = (size_t)(s0 + node0 + i);
            float ig = h2f(xiou[g * 768 + j])       + hus[i][j];
            float og = h2f(xiou[g * 768 + 256 + j]) + hus[i][256 + j];
            float ug = h2f(xiou[g * 768 + 512 + j]) + hus[i][512 + j];
            float f  = sigm(h2f(xfq[g * 512 + j])   + hus[i][768 + j]);
            size_t cb = (size_t)(cs + (node0 + i) * 4) * 256 + j;
            float csum = c_out[cb] + c_out[cb + 256] + c_out[cb + 512] + c_out[cb + 768];
            float cv = sigm(ig) * tanhf(ug) + f * csum;
            float hv = sigm(og) * tanhf(cv);
            h_out[g * 256 + j] = hv;
            c_out[g * 256 + j] = cv;
        }
    }
}

// ---------------------------------------------------------------------------
// Launch
// ---------------------------------------------------------------------------
extern "C" void kernel_launch(void* const* d_in, const int* in_sizes, int n_in,
                              void* d_out, int out_size)
{
    const float* x      = (const float*)d_in[0];
    const float* W_iou  = (const float*)d_in[1];
    const float* b_iou  = (const float*)d_in[2];
    const float* W_f    = (const float*)d_in[3];
    const float* b_f    = (const float*)d_in[4];
    const float* Wq     = (const float*)d_in[5];
    const float* bq     = (const float*)d_in[6];
    const float* Wk     = (const float*)d_in[7];
    const float* bk     = (const float*)d_in[8];
    const float* Wv     = (const float*)d_in[9];
    const float* bv     = (const float*)d_in[10];
    const float* Wl     = (const float*)d_in[11];
    const float* bl     = (const float*)d_in[12];
    const float* Uiou_w = (const float*)d_in[13];
    const float* Uiou_b = (const float*)d_in[14];
    const float* Uf_w   = (const float*)d_in[15];
    const float* Uf_b   = (const float*)d_in[16];

    float* h_out = (float*)d_out;
    float* c_out = h_out + (size_t)NN * 256;

    float *bias, *bcomb, *zbias;
    __half *xiou, *xfq, *hu, *kkvv, *att, *xh, *hh, *wthi, *wcombt, *wlplain;
    cudaGetSymbolAddress((void**)&xiou,    g_xiou);
    cudaGetSymbolAddress((void**)&xfq,     g_xfq);
    cudaGetSymbolAddress((void**)&hu,      g_hu);
    cudaGetSymbolAddress((void**)&bias,    g_bias);
    cudaGetSymbolAddress((void**)&bcomb,   g_bcomb);
    cudaGetSymbolAddress((void**)&zbias,   g_zbias);
    cudaGetSymbolAddress((void**)&kkvv,    g_kkvv);
    cudaGetSymbolAddress((void**)&att,     g_att);
    cudaGetSymbolAddress((void**)&xh,      g_xh);
    cudaGetSymbolAddress((void**)&hh,      g_hh);
    cudaGetSymbolAddress((void**)&wthi,    g_wthi);
    cudaGetSymbolAddress((void**)&wcombt,  g_wcombt);
    cudaGetSymbolAddress((void**)&wlplain, g_wlplain);

    cudaFuncSetAttribute(gemm_f16, cudaFuncAttributeMaxDynamicSharedMemorySize, GSMEM);

    auto GEMMB = [&](const __half* A, const __half* Brow, const float* bias_,
                     __half* Ch, int M, int Ntot) {
        dim3 grid((M + 127) / 128, Ntot / 256);
        gemm_f16<<<grid, 256, GSMEM>>>(A, Brow, bias_, Ch, M, Ntot);
    };
    auto GEMM = [&](const __half* A, int wt, __half* Ch, int M, int Ntot) {
        GEMMB(A, wthi + (size_t)wt * 256, bias + wt, Ch, M, Ntot);
    };

    // ---- combined weight prep (1 launch) ----
    PrepArgs pa;
    pa.W[0] = W_iou;  pa.N[0] = 768; pa.row_off[0] = WT_IOU;
    pa.W[1] = W_f;    pa.N[1] = 256; pa.row_off[1] = WT_FQ;
    pa.W[2] = Wq;     pa.N[2] = 256; pa.row_off[2] = WT_FQ + 256;
    pa.W[3] = Wk;     pa.N[3] = 256; pa.row_off[3] = WT_KV;
    pa.W[4] = Wv;     pa.N[4] = 256; pa.row_off[4] = WT_KV + 256;
    pa.W[5] = Wl;     pa.N[5] = 256; pa.row_off[5] = WT_L;
    pa.W[6] = Uiou_w; pa.N[6] = 768; pa.row_off[6] = WT_U;
    pa.W[7] = Uf_w;   pa.N[7] = 256; pa.row_off[7] = WT_U + 768;
    pa.blk_cum[0] = 0;
    for (int m = 0; m < 8; m++) pa.blk_cum[m + 1] = pa.blk_cum[m] + pa.N[m] / 32;
    prep_all<<<pa.blk_cum[8], 256>>>(pa, wthi);

    // ---- bias concat ----
    cudaMemcpyAsync(bias + WT_IOU,      b_iou,  768 * 4, cudaMemcpyDeviceToDevice, 0);
    cudaMemcpyAsync(bias + WT_FQ,       b_f,    256 * 4, cudaMemcpyDeviceToDevice, 0);
    cudaMemcpyAsync(bias + WT_FQ + 256, bq,     256 * 4, cudaMemcpyDeviceToDevice, 0);
    cudaMemcpyAsync(bias + WT_KV,       bk,     256 * 4, cudaMemcpyDeviceToDevice, 0);
    cudaMemcpyAsync(bias + WT_KV + 256, bv,     256 * 4, cudaMemcpyDeviceToDevice, 0);

    // ---- fold Wl into U:  wcombt[c,k] = sum_j U[j,c] * Wl[k,j]  (fp16) ----
    split_x<<<(256 * 256 / 4 + 255) / 256, 256>>>(Wl, wlplain, 256 * 256 / 4);
    GEMMB(wthi + (size_t)WT_U * 256, wlplain, zbias, wcombt, 1024, 256);
    bcomb_kernel<<<32, 256>>>(bl, Uiou_w, Uiou_b, Uf_w, Uf_b, bcomb);

    // ---- split x, precompute GEMMs ----
    const int tot4 = NN * 256 / 4;
    split_x<<<(tot4 + 255) / 256, 256>>>(x, xh, tot4);
    GEMM(xh, WT_IOU, xiou, NN, 768);       // N=768 -> grid.y=3
    GEMM(xh, WT_FQ,  xfq,  NI, 512);       // grid.y=2

    // ---- leaf level ----
    leaf_kernel<<<LEAF_N / 4, 256>>>(xiou, h_out, c_out, hh);

    // ---- internal levels, bottom-up ----
    const int starts[9] = {0, 1, 5, 21, 85, 341, 1365, 5461, 21845};
    for (int l = 7; l >= 4; l--) {
        const int n  = 1 << (2 * l);
        const int s0 = starts[l];
        const int cs = starts[l + 1];
        const int nK = n * 4;
        const __half* chh = hh + (size_t)cs * 256;

        GEMM(chh, WT_KV, kkvv, nK, 512);
        attn_kernel<<<n, 256>>>(xfq, kkvv, att, s0);
        GEMMB(att, wcombt, bcomb, hu, n, 1024);     // folded Wl+U
        combine_kernel<<<n, 256>>>(xiou, xfq, hu, h_out, c_out, hh, s0, cs);
    }
    for (int l = 3; l >= 0; l--) {
        const int n  = 1 << (2 * l);
        fused_level<<<(n + 1) / 2, 512>>>(xiou, xfq,
                                          Wk, bk, Wv, bv, Wl, bl,
                                          Uiou_w, Uiou_b, Uf_w, Uf_b,
                                          h_out, c_out,
                                          starts[l], starts[l + 1], n);
    }
}